// round 5
// baseline (speedup 1.0000x reference)
#include <cuda_runtime.h>
#include <math.h>
#include <stdint.h>

#define B_   8
#define NQ   8192
#define MK   2048
typedef unsigned short ushortT;
typedef unsigned int   uintT;

// ===================== helpers =====================
__device__ __forceinline__ uint32_t smem_to_u32(const void* p) {
    uint32_t a;
    asm("{ .reg .u64 t; cvta.to.shared.u64 t, %1; cvt.u32.u64 %0, t; }" : "=r"(a) : "l"(p));
    return a;
}
#define CP_ASYNC16(s, g) \
    asm volatile("cp.async.cg.shared.global [%0], [%1], 16;" :: "r"(s), "l"(g))
#define CP_COMMIT() asm volatile("cp.async.commit_group;")
#define CP_WAIT0()  asm volatile("cp.async.wait_group 0;")

__device__ __forceinline__ void ldsm4(uint32_t& r0, uint32_t& r1, uint32_t& r2, uint32_t& r3,
                                      uint32_t addr) {
    asm volatile("ldmatrix.sync.aligned.m8n8.x4.shared.b16 {%0,%1,%2,%3}, [%4];"
                 : "=r"(r0), "=r"(r1), "=r"(r2), "=r"(r3) : "r"(addr));
}
__device__ __forceinline__ void ldsm2(uint32_t& r0, uint32_t& r1, uint32_t addr) {
    asm volatile("ldmatrix.sync.aligned.m8n8.x2.shared.b16 {%0,%1}, [%2];"
                 : "=r"(r0), "=r"(r1) : "r"(addr));
}
__device__ __forceinline__ void mma16816(float* d, const uint32_t* a, const uint32_t* b) {
    asm volatile(
        "mma.sync.aligned.m16n8k16.row.col.f32.bf16.bf16.f32 "
        "{%0,%1,%2,%3}, {%4,%5,%6,%7}, {%8,%9}, {%0,%1,%2,%3};"
        : "+f"(d[0]), "+f"(d[1]), "+f"(d[2]), "+f"(d[3])
        : "r"(a[0]), "r"(a[1]), "r"(a[2]), "r"(a[3]), "r"(b[0]), "r"(b[1]));
}

// fp32 -> bf16 hi + bf16 lo (RNE)
__device__ __forceinline__ void split_bf(float v, ushortT& h, ushortT& l) {
    uintT u = __float_as_uint(v);
    uintT hb = (u + 0x7fffu + ((u >> 16) & 1u)) >> 16;
    h = (ushortT)hb;
    float r = v - __uint_as_float(hb << 16);
    uintT u2 = __float_as_uint(r);
    l = (ushortT)((u2 + 0x7fffu + ((u2 >> 16) & 1u)) >> 16);
}

// stable better-than: smaller distance wins; on tie, lower index (matches lax.top_k)
#define BETTER(da, ia, db, ib) ((da) < (db) || ((da) == (db) && (ia) < (ib)))
__device__ __forceinline__ void ins3(float& d0, int& i0, float& d1, int& i1,
                                     float& d2, int& i2, float dd, int m) {
    if (BETTER(dd, m, d2, i2)) {
        if (BETTER(dd, m, d1, i1)) {
            d2 = d1; i2 = i1;
            if (BETTER(dd, m, d0, i0)) { d1 = d0; i1 = i0; d0 = dd; i0 = m; }
            else                        { d1 = dd; i1 = m; }
        } else { d2 = dd; i2 = m; }
    }
}

// ===================== scratch =====================
__device__ ushortT gA1[(size_t)8 * 8192 * 1024];  // [H(512) | L(512)]
__device__ ushortT gA2[(size_t)8 * 8192 * 512];   // [H(256) | L(256)]
__device__ ushortT gW1[256 * 1536];               // [Wh | Wl | Wh]
__device__ ushortT gW2[256 * 768];
__device__ float g_h  [(size_t)8 * 8192 * 256];
__device__ float g_kfT[(size_t)8 * 2048 * 256];
__device__ int   g_idx[8 * 8192 * 3];
__device__ float g_wgt[8 * 8192 * 3];
__device__ float g_E  [8 * 8192];
__device__ float g_En [8 * 8192];
__device__ float g_sumA[8 * 32];
__device__ float g_ctx[8 * 256];
__device__ float g_al1[256], g_be1[256], g_al2[256], g_be2[256];
__device__ float g_c2[32];

// ===================== prep =====================
__global__ void prep_kernel(const float* __restrict__ cb1, const float* __restrict__ gg1,
                            const float* __restrict__ bb1, const float* __restrict__ mm1,
                            const float* __restrict__ vv1,
                            const float* __restrict__ cb2, const float* __restrict__ gg2,
                            const float* __restrict__ bb2, const float* __restrict__ mm2,
                            const float* __restrict__ vv2,
                            const float* __restrict__ cw)
{
    int i = blockIdx.x * blockDim.x + threadIdx.x;
    if (i < 256) {
        float s1 = gg1[i] * rsqrtf(vv1[i] + 1e-5f);
        g_al1[i] = s1;
        g_be1[i] = s1 * (cb1[i] - mm1[i]) + bb1[i];
        float s2 = gg2[i] * rsqrtf(vv2[i] + 1e-5f);
        g_al2[i] = s2;
        g_be2[i] = s2 * (cb2[i] - mm2[i]) + bb2[i];
    }
    if (i < 32) {
        float s = 0.f;
        const float* c = cw + i * 256;
        for (int d = 0; d < 256; d++) s += c[d] * c[d];
        g_c2[i] = s;
    }
    if (i < 8 * 32) g_sumA[i] = 0.f;
    if (i < 8 * 8192) g_E[i] = 0.f;
}

__global__ void expand_w_kernel(const float* __restrict__ w1, const float* __restrict__ w2)
{
    int i = blockIdx.x * 256 + threadIdx.x;
    if (i < 256 * 512) {
        int n = i >> 9, k = i & 511;
        ushortT h, l; split_bf(w1[i], h, l);
        gW1[n * 1536 + k] = h; gW1[n * 1536 + 512 + k] = l; gW1[n * 1536 + 1024 + k] = h;
    }
    if (i < 256 * 256) {
        int n = i >> 8, k = i & 255;
        ushortT h, l; split_bf(w2[i], h, l);
        gW2[n * 768 + k] = h; gW2[n * 768 + 256 + k] = l; gW2[n * 768 + 512 + k] = h;
    }
}

// ---------------- transpose known_feats (B,256,2048) -> (B,2048,256) ----------------
__global__ void tr_kf_kernel(const float* __restrict__ kf)
{
    __shared__ float tile[32][33];
    int b = blockIdx.z;
    int m0 = blockIdx.x * 32, c0 = blockIdx.y * 32;
    int tx = threadIdx.x, ty = threadIdx.y;
    const float* in = kf + (size_t)b * 256 * MK;
#pragma unroll
    for (int j = 0; j < 32; j += 8)
        tile[ty + j][tx] = in[(size_t)(c0 + ty + j) * MK + m0 + tx];
    __syncthreads();
    float* out = g_kfT + (size_t)b * MK * 256;
#pragma unroll
    for (int j = 0; j < 32; j += 8)
        out[(size_t)(m0 + ty + j) * 256 + c0 + tx] = tile[tx][ty + j];
}

// ---------------- transpose unknow_feats -> gA1 cols [256,512) H, [768,1024) L -------
__global__ void tr_unk_kernel(const float* __restrict__ uf)
{
    __shared__ float tile[32][33];
    int b = blockIdx.z;
    int n0 = blockIdx.x * 32, c0 = blockIdx.y * 32;
    int tx = threadIdx.x, ty = threadIdx.y;
    const float* in = uf + (size_t)b * 256 * NQ;
#pragma unroll
    for (int j = 0; j < 32; j += 8)
        tile[ty + j][tx] = in[(size_t)(c0 + ty + j) * NQ + n0 + tx];
    __syncthreads();
#pragma unroll
    for (int j = 0; j < 32; j += 8) {
        float v = tile[tx][ty + j];
        ushortT h, l; split_bf(v, h, l);
        size_t row = ((size_t)b * NQ + n0 + ty + j) * 1024;
        gA1[row + 256 + c0 + tx] = h;
        gA1[row + 768 + c0 + tx] = l;
    }
}

// ---------------- three_nn: 4 threads per query, 512-point chunks, shfl merge --------
__global__ __launch_bounds__(256) void three_nn_kernel(const float* __restrict__ unknown,
                                                       const float* __restrict__ known)
{
    __shared__ float4 kp[MK];           // all 2048 knowns (32 KB)
    int bz = blockIdx.y;
    int t  = threadIdx.x;
    int q  = blockIdx.x * 64 + (t >> 2);   // query index
    int ck = t & 3;                        // chunk id

    const float* kb = known + (size_t)bz * MK * 3;
    for (int i = t; i < MK; i += 256) {
        float kx = kb[i * 3 + 0];
        float ky = kb[i * 3 + 1];
        float kz = kb[i * 3 + 2];
        kp[i] = make_float4(kx, ky, kz, kx * kx + ky * ky + kz * kz);
    }
    __syncthreads();

    const float* u = unknown + ((size_t)bz * NQ + q) * 3;
    float ux = u[0], uy = u[1], uz = u[2];
    float x2 = ux * ux + uy * uy + uz * uz;

    float d0 = 1e30f, d1 = 1e30f, d2 = 1e30f;
    int   i0 = 0x7fffffff, i1 = 0x7fffffff, i2 = 0x7fffffff;
    int m0 = ck * 512;
#pragma unroll 4
    for (int j = 0; j < 512; j++) {
        float4 p = kp[m0 + j];
        float dd = x2 - 2.f * (ux * p.x + uy * p.y + uz * p.z) + p.w;
        ins3(d0, i0, d1, i1, d2, i2, dd, m0 + j);
    }

    // merge across the 4 chunk threads (lanes ck=0..3 within quad)
#pragma unroll
    for (int off = 1; off <= 2; off <<= 1) {
        float e0 = __shfl_xor_sync(0xffffffffu, d0, off);
        float e1 = __shfl_xor_sync(0xffffffffu, d1, off);
        float e2 = __shfl_xor_sync(0xffffffffu, d2, off);
        int   j0 = __shfl_xor_sync(0xffffffffu, i0, off);
        int   j1 = __shfl_xor_sync(0xffffffffu, i1, off);
        int   j2 = __shfl_xor_sync(0xffffffffu, i2, off);
        ins3(d0, i0, d1, i1, d2, i2, e0, j0);
        ins3(d0, i0, d1, i1, d2, i2, e1, j1);
        ins3(d0, i0, d1, i1, d2, i2, e2, j2);
    }

    if (ck == 0) {
        float r0 = 1.f / (sqrtf(fmaxf(d0, 1e-12f)) + 1e-8f);
        float r1 = 1.f / (sqrtf(fmaxf(d1, 1e-12f)) + 1e-8f);
        float r2 = 1.f / (sqrtf(fmaxf(d2, 1e-12f)) + 1e-8f);
        float rs = 1.f / (r0 + r1 + r2);
        size_t base = ((size_t)bz * NQ + q) * 3;
        g_idx[base + 0] = i0; g_idx[base + 1] = i1; g_idx[base + 2] = i2;
        g_wgt[base + 0] = r0 * rs; g_wgt[base + 1] = r1 * rs; g_wgt[base + 2] = r2 * rs;
    }
}

// ---------------- interpolate -> gA1 cols [0,256) H, [512,768) L ----------------
__global__ __launch_bounds__(256) void interp_kernel()
{
    int bz = blockIdx.y, t = threadIdx.x;
    int n = blockIdx.x * 2 + (t >> 7);
    int d = (t & 127) * 2;
    size_t base = ((size_t)bz * NQ + n) * 3;
    int i0 = g_idx[base], i1 = g_idx[base + 1], i2 = g_idx[base + 2];
    float w0 = g_wgt[base], w1 = g_wgt[base + 1], w2 = g_wgt[base + 2];
    const float* kf = g_kfT + (size_t)bz * MK * 256;
    float2 a = *(const float2*)&kf[(size_t)i0 * 256 + d];
    float2 b = *(const float2*)&kf[(size_t)i1 * 256 + d];
    float2 c = *(const float2*)&kf[(size_t)i2 * 256 + d];
    float v0 = w0 * a.x + w1 * b.x + w2 * c.x;
    float v1 = w0 * a.y + w1 * b.y + w2 * c.y;
    ushortT h0, l0, h1, l1;
    split_bf(v0, h0, l0); split_bf(v1, h1, l1);
    size_t row = ((size_t)bz * NQ + n) * 1024;
    *(uintT*)&gA1[row + d]       = (uintT)h0 | ((uintT)h1 << 16);
    *(uintT*)&gA1[row + 512 + d] = (uintT)l0 | ((uintT)l1 << 16);
}

// ===================== HMMA GEMM =====================
template <int L>
__global__ __launch_bounds__(256) void gemm_mma()
{
    constexpr int K   = (L == 1) ? 512 : 256;
    constexpr int CPB = K / 32;
    constexpr int NCH = 3 * CPB;
    constexpr int KA  = 2 * K;
    constexpr int KW  = 3 * K;
    const ushortT* Ag = (L == 1) ? gA1 : gA2;
    const ushortT* Wg = (L == 1) ? gW1 : gW2;
    const float* alpha = (L == 1) ? g_al1 : g_al2;
    const float* beta  = (L == 1) ? g_be1 : g_be2;

    __shared__ __align__(16) ushortT sA[2][128 * 32];
    __shared__ __align__(16) ushortT sB[2][128 * 32];
    __shared__ float s_al[128], s_be[128];

    int tid = threadIdx.x, wid = tid >> 5, lane = tid & 31;
    int bm = blockIdx.x * 128, bn = blockIdx.y * 128;
    if (tid < 128) { s_al[tid] = alpha[bn + tid]; s_be[tid] = beta[bn + tid]; }

    uint32_t sAb = smem_to_u32(sA);
    uint32_t sBb = smem_to_u32(sB);

    int lr = tid >> 1;
    int ls = (tid & 1) * 2;
    uint32_t off0 = lr * 64 + (((ls)     ^ (lr & 3)) << 4);
    uint32_t off1 = lr * 64 + (((ls + 1) ^ (lr & 3)) << 4);

    const ushortT* Arow = Ag + (size_t)(bm + lr) * KA;
    const ushortT* Wrow = Wg + (size_t)(bn + lr) * KW;

    {
        CP_ASYNC16(sAb + off0, Arow + ls * 8);
        CP_ASYNC16(sAb + off1, Arow + ls * 8 + 8);
        CP_ASYNC16(sBb + off0, Wrow + ls * 8);
        CP_ASYNC16(sBb + off1, Wrow + ls * 8 + 8);
        CP_COMMIT();
    }

    float c[4][4][4];
#pragma unroll
    for (int i = 0; i < 4; i++)
#pragma unroll
        for (int j = 0; j < 4; j++)
#pragma unroll
            for (int q = 0; q < 4; q++) c[i][j][q] = 0.f;

    int wm = wid >> 2, wn = wid & 3;

    for (int kc = 0; kc < NCH; kc++) {
        CP_WAIT0();
        __syncthreads();
        int st = kc & 1;
        if (kc + 1 < NCH) {
            int kn = kc + 1;
            int blk = kn / CPB;
            int acol = (blk == 2 ? K : 0) + (kn % CPB) * 32;
            int wcol = kn * 32;
            uint32_t as = sAb + ((kn & 1) ? 8192 : 0);
            uint32_t ws = sBb + ((kn & 1) ? 8192 : 0);
            CP_ASYNC16(as + off0, Arow + acol + ls * 8);
            CP_ASYNC16(as + off1, Arow + acol + ls * 8 + 8);
            CP_ASYNC16(ws + off0, Wrow + wcol + ls * 8);
            CP_ASYNC16(ws + off1, Wrow + wcol + ls * 8 + 8);
            CP_COMMIT();
        }
        uint32_t aBase = sAb + st * 8192;
        uint32_t bBase = sBb + st * 8192;
#pragma unroll
        for (int kk = 0; kk < 2; kk++) {
            uint32_t afr[4][4], bfr[4][2];
#pragma unroll
            for (int mt = 0; mt < 4; mt++) {
                int r = wm * 64 + mt * 16 + (lane & 15);
                int s = kk * 2 + (lane >> 4);
                ldsm4(afr[mt][0], afr[mt][1], afr[mt][2], afr[mt][3],
                      aBase + r * 64 + ((s ^ (r & 3)) << 4));
            }
#pragma unroll
            for (int nt = 0; nt < 4; nt++) {
                int r = wn * 32 + nt * 8 + (lane & 7);
                int s = kk * 2 + ((lane >> 3) & 1);
                ldsm2(bfr[nt][0], bfr[nt][1],
                      bBase + r * 64 + ((s ^ (r & 3)) << 4));
            }
#pragma unroll
            for (int mt = 0; mt < 4; mt++)
#pragma unroll
                for (int nt = 0; nt < 4; nt++)
                    mma16816(c[mt][nt], afr[mt], bfr[nt]);
        }
        __syncthreads();
    }

#pragma unroll
    for (int mt = 0; mt < 4; mt++) {
#pragma unroll
        for (int nt = 0; nt < 4; nt++) {
            int cl = wn * 32 + nt * 8 + (lane & 3) * 2;
            int gcol = bn + cl;
            int rl = wm * 64 + mt * 16 + (lane >> 2);
#pragma unroll
            for (int hh = 0; hh < 2; hh++) {
                int grow = bm + rl + hh * 8;
                float v0 = fmaxf(fmaf(c[mt][nt][hh * 2 + 0], s_al[cl],     s_be[cl]),     0.f);
                float v1 = fmaxf(fmaf(c[mt][nt][hh * 2 + 1], s_al[cl + 1], s_be[cl + 1]), 0.f);
                if (L == 1) {
                    ushortT h0, l0, h1, l1;
                    split_bf(v0, h0, l0); split_bf(v1, h1, l1);
                    *(uintT*)&gA2[(size_t)grow * 512 + gcol]       = (uintT)h0 | ((uintT)h1 << 16);
                    *(uintT*)&gA2[(size_t)grow * 512 + 256 + gcol] = (uintT)l0 | ((uintT)l1 << 16);
                } else {
                    float2 o = make_float2(v0, v1);
                    *(float2*)&g_h[(size_t)grow * 256 + gcol] = o;
                }
            }
        }
    }
}

// ---------------- encoding ----------------
__global__ __launch_bounds__(256) void encoding_kernel(const float* __restrict__ cw,
                                                       const float* __restrict__ scale)
{
    __shared__ float cwT[256][32];
    __shared__ float Ash[64][32];
    __shared__ float c2s[32], scs[32];
    int bz = blockIdx.y;
    int n0 = blockIdx.x * 64;
    int t = threadIdx.x, warp = t >> 5, lane = t & 31;
    for (int i = t; i < 32 * 256; i += 256) cwT[i & 255][i >> 8] = cw[i];
    if (t < 32) { c2s[t] = g_c2[t]; scs[t] = scale[t]; }
    __syncthreads();
    const float* Xb = g_h + ((size_t)bz * NQ + n0) * 256;
    for (int pi = 0; pi < 8; pi++) {
        int p = warp * 8 + pi;
        const float* xp = Xb + (size_t)p * 256;
        float xr[8];
#pragma unroll
        for (int j = 0; j < 8; j++) xr[j] = xp[j * 32 + lane];
        float xn2 = 0.f;
#pragma unroll
        for (int j = 0; j < 8; j++) xn2 = fmaf(xr[j], xr[j], xn2);
#pragma unroll
        for (int o = 16; o > 0; o >>= 1) xn2 += __shfl_xor_sync(0xffffffffu, xn2, o);
        float dotv = 0.f;
#pragma unroll
        for (int j = 0; j < 8; j++) {
            float xj = xr[j];
#pragma unroll
            for (int l2 = 0; l2 < 32; l2++) {
                float x = __shfl_sync(0xffffffffu, xj, l2);
                dotv = fmaf(x, cwT[j * 32 + l2][lane], dotv);
            }
        }
        float sl = scs[lane] * (xn2 - 2.f * dotv + c2s[lane]);
        float mx = sl;
#pragma unroll
        for (int o = 16; o > 0; o >>= 1) mx = fmaxf(mx, __shfl_xor_sync(0xffffffffu, mx, o));
        float e = __expf(sl - mx);
        float se = e;
#pragma unroll
        for (int o = 16; o > 0; o >>= 1) se += __shfl_xor_sync(0xffffffffu, se, o);
        Ash[p][lane] = e / se;
    }
    __syncthreads();
    if (t < 32) {
        float s = 0.f;
        for (int p = 0; p < 64; p++) s += Ash[p][t];
        atomicAdd(&g_sumA[bz * 32 + t], s);
    }
    float acc[32];
#pragma unroll
    for (int k = 0; k < 32; k++) acc[k] = 0.f;
    for (int p = 0; p < 64; p++) {
        float x = Xb[(size_t)p * 256 + t];
#pragma unroll
        for (int k = 0; k < 32; k++) acc[k] = fmaf(Ash[p][k], x, acc[k]);
    }
    float* Eb = g_E + (size_t)bz * 8192;
#pragma unroll
    for (int k = 0; k < 32; k++) atomicAdd(&Eb[k * 256 + t], acc[k]);
}

__global__ __launch_bounds__(256) void enc_fin_kernel(const float* __restrict__ cw)
{
    __shared__ float red[256];
    int bz = blockIdx.x, t = threadIdx.x;
    float ss = 0.f;
    for (int j = t; j < 8192; j += 256) {
        float v = g_E[bz * 8192 + j] - g_sumA[bz * 32 + (j >> 8)] * cw[j];
        v = fmaxf(v, 0.f);
        g_En[bz * 8192 + j] = v;
        ss += v * v;
    }
    red[t] = ss;
    __syncthreads();
    for (int s = 128; s > 0; s >>= 1) {
        if (t < s) red[t] += red[t + s];
        __syncthreads();
    }
    float rinv = 1.f / fmaxf(sqrtf(red[0]), 1e-12f);
    for (int j = t; j < 8192; j += 256) g_En[bz * 8192 + j] *= rinv;
}

__global__ __launch_bounds__(256) void ctx_gemv_kernel(const float* __restrict__ lin_w,
                                                       const float* __restrict__ lin_b)
{
    __shared__ float red[8][256];
    int o = blockIdx.x, t = threadIdx.x;
    float acc[8];
#pragma unroll
    for (int b = 0; b < 8; b++) acc[b] = 0.f;
    const float* wrow = lin_w + (size_t)o * 8192;
    for (int j = t; j < 8192; j += 256) {
        float w = wrow[j];
#pragma unroll
        for (int b = 0; b < 8; b++) acc[b] = fmaf(w, g_En[b * 8192 + j], acc[b]);
    }
#pragma unroll
    for (int b = 0; b < 8; b++) red[b][t] = acc[b];
    __syncthreads();
    for (int s = 128; s > 0; s >>= 1) {
        if (t < s) {
#pragma unroll
            for (int b = 0; b < 8; b++) red[b][t] += red[b][t + s];
        }
        __syncthreads();
    }
    if (t < 8) {
        float z = red[t][0] + lin_b[o];
        g_ctx[t * 256 + o] = 1.f / (1.f + expf(-z));
    }
}

__global__ void final_kernel(float* __restrict__ out)
{
    __shared__ float tile[32][33];
    int bz = blockIdx.z;
    int d0 = blockIdx.x * 32, n0 = blockIdx.y * 32;
    int tx = threadIdx.x, ty = threadIdx.y;
    const float* h = g_h + (size_t)bz * NQ * 256;
#pragma unroll
    for (int j = 0; j < 32; j += 8)
        tile[ty + j][tx] = h[(size_t)(n0 + ty + j) * 256 + d0 + tx];
    __syncthreads();
    float* ob = out + (size_t)bz * 256 * NQ;
#pragma unroll
    for (int j = 0; j < 32; j += 8)
        ob[(size_t)(d0 + ty + j) * NQ + n0 + tx] = tile[tx][ty + j] * g_ctx[bz * 256 + d0 + ty + j];
}

// ===================== launcher =====================
extern "C" void kernel_launch(void* const* d_in, const int* in_sizes, int n_in,
                              void* d_out, int out_size)
{
    (void)in_sizes; (void)n_in; (void)out_size;
    const float* unknown      = (const float*)d_in[0];
    const float* known        = (const float*)d_in[1];
    const float* unknow_feats = (const float*)d_in[2];
    const float* known_feats  = (const float*)d_in[3];
    const float* conv_w1 = (const float*)d_in[4];
    const float* conv_b1 = (const float*)d_in[5];
    const float* bn_g1 = (const float*)d_in[6];
    const float* bn_b1 = (const float*)d_in[7];
    const float* bn_m1 = (const float*)d_in[8];
    const float* bn_v1 = (const float*)d_in[9];
    const float* conv_w2 = (const float*)d_in[10];
    const float* conv_b2 = (const float*)d_in[11];
    const float* bn_g2 = (const float*)d_in[12];
    const float* bn_b2 = (const float*)d_in[13];
    const float* bn_m2 = (const float*)d_in[14];
    const float* bn_v2 = (const float*)d_in[15];
    const float* enc_cw    = (const float*)d_in[16];
    const float* enc_scale = (const float*)d_in[17];
    const float* lin_w     = (const float*)d_in[18];
    const float* lin_b     = (const float*)d_in[19];
    float* out = (float*)d_out;

    prep_kernel<<<256, 256>>>(conv_b1, bn_g1, bn_b1, bn_m1, bn_v1,
                              conv_b2, bn_g2, bn_b2, bn_m2, bn_v2, enc_cw);
    expand_w_kernel<<<512, 256>>>(conv_w1, conv_w2);
    tr_kf_kernel<<<dim3(64, 8, 8), dim3(32, 8)>>>(known_feats);
    three_nn_kernel<<<dim3(NQ / 64, B_), 256>>>(unknown, known);
    interp_kernel<<<dim3(NQ / 2, B_), 256>>>();
    tr_unk_kernel<<<dim3(NQ / 32, 8, B_), dim3(32, 8)>>>(unknow_feats);
    gemm_mma<1><<<dim3(512, 2), 256>>>();
    gemm_mma<2><<<dim3(512, 2), 256>>>();
    encoding_kernel<<<dim3(NQ / 64, B_), 256>>>(enc_cw, enc_scale);
    enc_fin_kernel<<<B_, 256>>>(enc_cw);
    ctx_gemv_kernel<<<256, 256>>>(lin_w, lin_b);
    final_kernel<<<dim3(8, NQ / 32, B_), dim3(32, 8)>>>(out);
}

// round 6
// speedup vs baseline: 1.2962x; 1.2962x over previous
#include <cuda_runtime.h>
#include <math.h>
#include <stdint.h>

#define B_   8
#define NQ   8192
#define MK   2048
typedef unsigned short ushortT;
typedef unsigned int   uintT;

// ===================== helpers =====================
__device__ __forceinline__ uint32_t smem_to_u32(const void* p) {
    uint32_t a;
    asm("{ .reg .u64 t; cvta.to.shared.u64 t, %1; cvt.u32.u64 %0, t; }" : "=r"(a) : "l"(p));
    return a;
}
#define CP_ASYNC16(s, g) \
    asm volatile("cp.async.cg.shared.global [%0], [%1], 16;" :: "r"(s), "l"(g))
#define CP_COMMIT() asm volatile("cp.async.commit_group;")
#define CP_WAIT0()  asm volatile("cp.async.wait_group 0;")

__device__ __forceinline__ void ldsm4(uint32_t& r0, uint32_t& r1, uint32_t& r2, uint32_t& r3,
                                      uint32_t addr) {
    asm volatile("ldmatrix.sync.aligned.m8n8.x4.shared.b16 {%0,%1,%2,%3}, [%4];"
                 : "=r"(r0), "=r"(r1), "=r"(r2), "=r"(r3) : "r"(addr));
}
__device__ __forceinline__ void ldsm2(uint32_t& r0, uint32_t& r1, uint32_t addr) {
    asm volatile("ldmatrix.sync.aligned.m8n8.x2.shared.b16 {%0,%1}, [%2];"
                 : "=r"(r0), "=r"(r1) : "r"(addr));
}
__device__ __forceinline__ void mma16816(float* d, const uint32_t* a, const uint32_t* b) {
    asm volatile(
        "mma.sync.aligned.m16n8k16.row.col.f32.bf16.bf16.f32 "
        "{%0,%1,%2,%3}, {%4,%5,%6,%7}, {%8,%9}, {%0,%1,%2,%3};"
        : "+f"(d[0]), "+f"(d[1]), "+f"(d[2]), "+f"(d[3])
        : "r"(a[0]), "r"(a[1]), "r"(a[2]), "r"(a[3]), "r"(b[0]), "r"(b[1]));
}

// fp32 -> bf16 hi + bf16 lo (RNE)
__device__ __forceinline__ void split_bf(float v, ushortT& h, ushortT& l) {
    uintT u = __float_as_uint(v);
    uintT hb = (u + 0x7fffu + ((u >> 16) & 1u)) >> 16;
    h = (ushortT)hb;
    float r = v - __uint_as_float(hb << 16);
    uintT u2 = __float_as_uint(r);
    l = (ushortT)((u2 + 0x7fffu + ((u2 >> 16) & 1u)) >> 16);
}

__device__ __forceinline__ void ins3(float& d0, int& i0, float& d1, int& i1,
                                     float& d2, int& i2, float dd, int m) {
    if (dd < d2) {
        if (dd < d1) {
            d2 = d1; i2 = i1;
            if (dd < d0) { d1 = d0; i1 = i0; d0 = dd; i0 = m; }
            else          { d1 = dd; i1 = m; }
        } else { d2 = dd; i2 = m; }
    }
}

// ===================== scratch =====================
__device__ ushortT gA1[(size_t)8 * 8192 * 1024];  // [H(512) | L(512)]
__device__ ushortT gA2[(size_t)8 * 8192 * 512];   // [H(256) | L(256)]
__device__ ushortT gW1[256 * 1536];               // [Wh | Wl | Wh]
__device__ ushortT gW2[256 * 768];
__device__ float g_h  [(size_t)8 * 8192 * 256];
__device__ float g_kfT[(size_t)8 * 2048 * 256];
__device__ int   g_idx[8 * 8192 * 3];
__device__ float g_wgt[8 * 8192 * 3];
__device__ float g_E  [8 * 8192];
__device__ float g_En [8 * 8192];
__device__ float g_sumA[8 * 32];
__device__ float g_ctx[8 * 256];
__device__ float g_al1[256], g_be1[256], g_al2[256], g_be2[256];
__device__ float g_c2[32];

// ===================== prep =====================
__global__ void prep_kernel(const float* __restrict__ cb1, const float* __restrict__ gg1,
                            const float* __restrict__ bb1, const float* __restrict__ mm1,
                            const float* __restrict__ vv1,
                            const float* __restrict__ cb2, const float* __restrict__ gg2,
                            const float* __restrict__ bb2, const float* __restrict__ mm2,
                            const float* __restrict__ vv2,
                            const float* __restrict__ cw)
{
    int i = blockIdx.x * blockDim.x + threadIdx.x;
    if (i < 256) {
        float s1 = gg1[i] * rsqrtf(vv1[i] + 1e-5f);
        g_al1[i] = s1;
        g_be1[i] = s1 * (cb1[i] - mm1[i]) + bb1[i];
        float s2 = gg2[i] * rsqrtf(vv2[i] + 1e-5f);
        g_al2[i] = s2;
        g_be2[i] = s2 * (cb2[i] - mm2[i]) + bb2[i];
    }
    if (i < 32) {
        float s = 0.f;
        const float* c = cw + i * 256;
        for (int d = 0; d < 256; d++) s += c[d] * c[d];
        g_c2[i] = s;
    }
    if (i < 8 * 32) g_sumA[i] = 0.f;
    if (i < 8 * 8192) g_E[i] = 0.f;
}

__global__ void expand_w_kernel(const float* __restrict__ w1, const float* __restrict__ w2)
{
    int i = blockIdx.x * 256 + threadIdx.x;
    if (i < 256 * 512) {
        int n = i >> 9, k = i & 511;
        ushortT h, l; split_bf(w1[i], h, l);
        gW1[n * 1536 + k] = h; gW1[n * 1536 + 512 + k] = l; gW1[n * 1536 + 1024 + k] = h;
    }
    if (i < 256 * 256) {
        int n = i >> 8, k = i & 255;
        ushortT h, l; split_bf(w2[i], h, l);
        gW2[n * 768 + k] = h; gW2[n * 768 + 256 + k] = l; gW2[n * 768 + 512 + k] = h;
    }
}

// ---------------- transpose known_feats (B,256,2048) -> (B,2048,256) ----------------
__global__ void tr_kf_kernel(const float* __restrict__ kf)
{
    __shared__ float tile[32][33];
    int b = blockIdx.z;
    int m0 = blockIdx.x * 32, c0 = blockIdx.y * 32;
    int tx = threadIdx.x, ty = threadIdx.y;
    const float* in = kf + (size_t)b * 256 * MK;
#pragma unroll
    for (int j = 0; j < 32; j += 8)
        tile[ty + j][tx] = in[(size_t)(c0 + ty + j) * MK + m0 + tx];
    __syncthreads();
    float* out = g_kfT + (size_t)b * MK * 256;
#pragma unroll
    for (int j = 0; j < 32; j += 8)
        out[(size_t)(m0 + ty + j) * 256 + c0 + tx] = tile[tx][ty + j];
}

// ---------------- transpose unknow_feats -> gA1 cols [256,512) H, [768,1024) L -------
__global__ void tr_unk_kernel(const float* __restrict__ uf)
{
    __shared__ float tile[32][33];
    int b = blockIdx.z;
    int n0 = blockIdx.x * 32, c0 = blockIdx.y * 32;
    int tx = threadIdx.x, ty = threadIdx.y;
    const float* in = uf + (size_t)b * 256 * NQ;
#pragma unroll
    for (int j = 0; j < 32; j += 8)
        tile[ty + j][tx] = in[(size_t)(c0 + ty + j) * NQ + n0 + tx];
    __syncthreads();
#pragma unroll
    for (int j = 0; j < 32; j += 8) {
        float v = tile[tx][ty + j];
        ushortT h, l; split_bf(v, h, l);
        size_t row = ((size_t)b * NQ + n0 + ty + j) * 1024;
        gA1[row + 256 + c0 + tx] = h;
        gA1[row + 768 + c0 + tx] = l;
    }
}

// ---------------- three_nn: 4 threads/query, padded chunks (conflict-free) ----------
#define CHPAD 513
__global__ __launch_bounds__(256) void three_nn_kernel(const float* __restrict__ unknown,
                                                       const float* __restrict__ known)
{
    __shared__ float4 kp[4 * CHPAD];     // chunk ck at base ck*513 -> banks offset by 4ck
    int bz = blockIdx.y;
    int t  = threadIdx.x;
    int q  = blockIdx.x * 64 + (t >> 2);
    int ck = t & 3;

    const float* kb = known + (size_t)bz * MK * 3;
    for (int i = t; i < MK; i += 256) {
        float kx = kb[i * 3 + 0];
        float ky = kb[i * 3 + 1];
        float kz = kb[i * 3 + 2];
        kp[(i >> 9) * CHPAD + (i & 511)] = make_float4(kx, ky, kz, kx * kx + ky * ky + kz * kz);
    }
    __syncthreads();

    const float* u = unknown + ((size_t)bz * NQ + q) * 3;
    float ux = u[0], uy = u[1], uz = u[2];
    float x2 = ux * ux + uy * uy + uz * uz;

    float d0 = 1e30f, d1 = 1e30f, d2 = 1e30f;
    int   i0 = 0, i1 = 0, i2 = 0;
    const float4* base = kp + ck * CHPAD;
    int m0 = ck * 512;
#pragma unroll 4
    for (int j = 0; j < 512; j++) {
        float4 p = base[j];
        float dd = x2 - 2.f * (ux * p.x + uy * p.y + uz * p.z) + p.w;
        ins3(d0, i0, d1, i1, d2, i2, dd, m0 + j);
    }

    // merge the 4 chunk-local top-3 sets (quad lanes ck=0..3)
#pragma unroll
    for (int off = 1; off <= 2; off <<= 1) {
        float e0 = __shfl_xor_sync(0xffffffffu, d0, off);
        float e1 = __shfl_xor_sync(0xffffffffu, d1, off);
        float e2 = __shfl_xor_sync(0xffffffffu, d2, off);
        int   j0 = __shfl_xor_sync(0xffffffffu, i0, off);
        int   j1 = __shfl_xor_sync(0xffffffffu, i1, off);
        int   j2 = __shfl_xor_sync(0xffffffffu, i2, off);
        ins3(d0, i0, d1, i1, d2, i2, e0, j0);
        ins3(d0, i0, d1, i1, d2, i2, e1, j1);
        ins3(d0, i0, d1, i1, d2, i2, e2, j2);
    }

    if (ck == 0) {
        float r0 = 1.f / (sqrtf(fmaxf(d0, 1e-12f)) + 1e-8f);
        float r1 = 1.f / (sqrtf(fmaxf(d1, 1e-12f)) + 1e-8f);
        float r2 = 1.f / (sqrtf(fmaxf(d2, 1e-12f)) + 1e-8f);
        float rs = 1.f / (r0 + r1 + r2);
        size_t base2 = ((size_t)bz * NQ + q) * 3;
        g_idx[base2 + 0] = i0; g_idx[base2 + 1] = i1; g_idx[base2 + 2] = i2;
        g_wgt[base2 + 0] = r0 * rs; g_wgt[base2 + 1] = r1 * rs; g_wgt[base2 + 2] = r2 * rs;
    }
}

// ---------------- interpolate -> gA1 cols [0,256) H, [512,768) L ----------------
__global__ __launch_bounds__(256) void interp_kernel()
{
    int bz = blockIdx.y, t = threadIdx.x;
    int n = blockIdx.x * 2 + (t >> 7);
    int d = (t & 127) * 2;
    size_t base = ((size_t)bz * NQ + n) * 3;
    int i0 = g_idx[base], i1 = g_idx[base + 1], i2 = g_idx[base + 2];
    float w0 = g_wgt[base], w1 = g_wgt[base + 1], w2 = g_wgt[base + 2];
    const float* kf = g_kfT + (size_t)bz * MK * 256;
    float2 a = *(const float2*)&kf[(size_t)i0 * 256 + d];
    float2 b = *(const float2*)&kf[(size_t)i1 * 256 + d];
    float2 c = *(const float2*)&kf[(size_t)i2 * 256 + d];
    float v0 = w0 * a.x + w1 * b.x + w2 * c.x;
    float v1 = w0 * a.y + w1 * b.y + w2 * c.y;
    ushortT h0, l0, h1, l1;
    split_bf(v0, h0, l0); split_bf(v1, h1, l1);
    size_t row = ((size_t)bz * NQ + n) * 1024;
    *(uintT*)&gA1[row + d]       = (uintT)h0 | ((uintT)h1 << 16);
    *(uintT*)&gA1[row + 512 + d] = (uintT)l0 | ((uintT)l1 << 16);
}

// ===================== HMMA GEMM =====================
template <int L>
__global__ __launch_bounds__(256) void gemm_mma()
{
    constexpr int K   = (L == 1) ? 512 : 256;
    constexpr int CPB = K / 32;
    constexpr int NCH = 3 * CPB;
    constexpr int KA  = 2 * K;
    constexpr int KW  = 3 * K;
    const ushortT* Ag = (L == 1) ? gA1 : gA2;
    const ushortT* Wg = (L == 1) ? gW1 : gW2;
    const float* alpha = (L == 1) ? g_al1 : g_al2;
    const float* beta  = (L == 1) ? g_be1 : g_be2;

    __shared__ __align__(16) ushortT sA[2][128 * 32];
    __shared__ __align__(16) ushortT sB[2][128 * 32];
    __shared__ float s_al[128], s_be[128];

    int tid = threadIdx.x, wid = tid >> 5, lane = tid & 31;
    int bm = blockIdx.x * 128, bn = blockIdx.y * 128;
    if (tid < 128) { s_al[tid] = alpha[bn + tid]; s_be[tid] = beta[bn + tid]; }

    uint32_t sAb = smem_to_u32(sA);
    uint32_t sBb = smem_to_u32(sB);

    int lr = tid >> 1;
    int ls = (tid & 1) * 2;
    uint32_t off0 = lr * 64 + (((ls)     ^ (lr & 3)) << 4);
    uint32_t off1 = lr * 64 + (((ls + 1) ^ (lr & 3)) << 4);

    const ushortT* Arow = Ag + (size_t)(bm + lr) * KA;
    const ushortT* Wrow = Wg + (size_t)(bn + lr) * KW;

    {
        CP_ASYNC16(sAb + off0, Arow + ls * 8);
        CP_ASYNC16(sAb + off1, Arow + ls * 8 + 8);
        CP_ASYNC16(sBb + off0, Wrow + ls * 8);
        CP_ASYNC16(sBb + off1, Wrow + ls * 8 + 8);
        CP_COMMIT();
    }

    float c[4][4][4];
#pragma unroll
    for (int i = 0; i < 4; i++)
#pragma unroll
        for (int j = 0; j < 4; j++)
#pragma unroll
            for (int q = 0; q < 4; q++) c[i][j][q] = 0.f;

    int wm = wid >> 2, wn = wid & 3;

    for (int kc = 0; kc < NCH; kc++) {
        CP_WAIT0();
        __syncthreads();
        int st = kc & 1;
        if (kc + 1 < NCH) {
            int kn = kc + 1;
            int blk = kn / CPB;
            int acol = (blk == 2 ? K : 0) + (kn % CPB) * 32;
            int wcol = kn * 32;
            uint32_t as = sAb + ((kn & 1) ? 8192 : 0);
            uint32_t ws = sBb + ((kn & 1) ? 8192 : 0);
            CP_ASYNC16(as + off0, Arow + acol + ls * 8);
            CP_ASYNC16(as + off1, Arow + acol + ls * 8 + 8);
            CP_ASYNC16(ws + off0, Wrow + wcol + ls * 8);
            CP_ASYNC16(ws + off1, Wrow + wcol + ls * 8 + 8);
            CP_COMMIT();
        }
        uint32_t aBase = sAb + st * 8192;
        uint32_t bBase = sBb + st * 8192;
#pragma unroll
        for (int kk = 0; kk < 2; kk++) {
            uint32_t afr[4][4], bfr[4][2];
#pragma unroll
            for (int mt = 0; mt < 4; mt++) {
                int r = wm * 64 + mt * 16 + (lane & 15);
                int s = kk * 2 + (lane >> 4);
                ldsm4(afr[mt][0], afr[mt][1], afr[mt][2], afr[mt][3],
                      aBase + r * 64 + ((s ^ (r & 3)) << 4));
            }
#pragma unroll
            for (int nt = 0; nt < 4; nt++) {
                int r = wn * 32 + nt * 8 + (lane & 7);
                int s = kk * 2 + ((lane >> 3) & 1);
                ldsm2(bfr[nt][0], bfr[nt][1],
                      bBase + r * 64 + ((s ^ (r & 3)) << 4));
            }
#pragma unroll
            for (int mt = 0; mt < 4; mt++)
#pragma unroll
                for (int nt = 0; nt < 4; nt++)
                    mma16816(c[mt][nt], afr[mt], bfr[nt]);
        }
        __syncthreads();
    }

#pragma unroll
    for (int mt = 0; mt < 4; mt++) {
#pragma unroll
        for (int nt = 0; nt < 4; nt++) {
            int cl = wn * 32 + nt * 8 + (lane & 3) * 2;
            int gcol = bn + cl;
            int rl = wm * 64 + mt * 16 + (lane >> 2);
#pragma unroll
            for (int hh = 0; hh < 2; hh++) {
                int grow = bm + rl + hh * 8;
                float v0 = fmaxf(fmaf(c[mt][nt][hh * 2 + 0], s_al[cl],     s_be[cl]),     0.f);
                float v1 = fmaxf(fmaf(c[mt][nt][hh * 2 + 1], s_al[cl + 1], s_be[cl + 1]), 0.f);
                if (L == 1) {
                    ushortT h0, l0, h1, l1;
                    split_bf(v0, h0, l0); split_bf(v1, h1, l1);
                    *(uintT*)&gA2[(size_t)grow * 512 + gcol]       = (uintT)h0 | ((uintT)h1 << 16);
                    *(uintT*)&gA2[(size_t)grow * 512 + 256 + gcol] = (uintT)l0 | ((uintT)l1 << 16);
                } else {
                    float2 o = make_float2(v0, v1);
                    *(float2*)&g_h[(size_t)grow * 256 + gcol] = o;
                }
            }
        }
    }
}

// ---------------- encoding ----------------
__global__ __launch_bounds__(256) void encoding_kernel(const float* __restrict__ cw,
                                                       const float* __restrict__ scale)
{
    __shared__ float cwT[256][32];
    __shared__ float Ash[64][32];
    __shared__ float c2s[32], scs[32];
    int bz = blockIdx.y;
    int n0 = blockIdx.x * 64;
    int t = threadIdx.x, warp = t >> 5, lane = t & 31;
    for (int i = t; i < 32 * 256; i += 256) cwT[i & 255][i >> 8] = cw[i];
    if (t < 32) { c2s[t] = g_c2[t]; scs[t] = scale[t]; }
    __syncthreads();
    const float* Xb = g_h + ((size_t)bz * NQ + n0) * 256;
    for (int pi = 0; pi < 8; pi++) {
        int p = warp * 8 + pi;
        const float* xp = Xb + (size_t)p * 256;
        float xr[8];
#pragma unroll
        for (int j = 0; j < 8; j++) xr[j] = xp[j * 32 + lane];
        float xn2 = 0.f;
#pragma unroll
        for (int j = 0; j < 8; j++) xn2 = fmaf(xr[j], xr[j], xn2);
#pragma unroll
        for (int o = 16; o > 0; o >>= 1) xn2 += __shfl_xor_sync(0xffffffffu, xn2, o);
        float dotv = 0.f;
#pragma unroll
        for (int j = 0; j < 8; j++) {
            float xj = xr[j];
#pragma unroll
            for (int l2 = 0; l2 < 32; l2++) {
                float x = __shfl_sync(0xffffffffu, xj, l2);
                dotv = fmaf(x, cwT[j * 32 + l2][lane], dotv);
            }
        }
        float sl = scs[lane] * (xn2 - 2.f * dotv + c2s[lane]);
        float mx = sl;
#pragma unroll
        for (int o = 16; o > 0; o >>= 1) mx = fmaxf(mx, __shfl_xor_sync(0xffffffffu, mx, o));
        float e = __expf(sl - mx);
        float se = e;
#pragma unroll
        for (int o = 16; o > 0; o >>= 1) se += __shfl_xor_sync(0xffffffffu, se, o);
        Ash[p][lane] = e / se;
    }
    __syncthreads();
    if (t < 32) {
        float s = 0.f;
        for (int p = 0; p < 64; p++) s += Ash[p][t];
        atomicAdd(&g_sumA[bz * 32 + t], s);
    }
    float acc[32];
#pragma unroll
    for (int k = 0; k < 32; k++) acc[k] = 0.f;
    for (int p = 0; p < 64; p++) {
        float x = Xb[(size_t)p * 256 + t];
#pragma unroll
        for (int k = 0; k < 32; k++) acc[k] = fmaf(Ash[p][k], x, acc[k]);
    }
    float* Eb = g_E + (size_t)bz * 8192;
#pragma unroll
    for (int k = 0; k < 32; k++) atomicAdd(&Eb[k * 256 + t], acc[k]);
}

__global__ __launch_bounds__(256) void enc_fin_kernel(const float* __restrict__ cw)
{
    __shared__ float red[256];
    int bz = blockIdx.x, t = threadIdx.x;
    float ss = 0.f;
    for (int j = t; j < 8192; j += 256) {
        float v = g_E[bz * 8192 + j] - g_sumA[bz * 32 + (j >> 8)] * cw[j];
        v = fmaxf(v, 0.f);
        g_En[bz * 8192 + j] = v;
        ss += v * v;
    }
    red[t] = ss;
    __syncthreads();
    for (int s = 128; s > 0; s >>= 1) {
        if (t < s) red[t] += red[t + s];
        __syncthreads();
    }
    float rinv = 1.f / fmaxf(sqrtf(red[0]), 1e-12f);
    for (int j = t; j < 8192; j += 256) g_En[bz * 8192 + j] *= rinv;
}

__global__ __launch_bounds__(256) void ctx_gemv_kernel(const float* __restrict__ lin_w,
                                                       const float* __restrict__ lin_b)
{
    __shared__ float red[8][256];
    int o = blockIdx.x, t = threadIdx.x;
    float acc[8];
#pragma unroll
    for (int b = 0; b < 8; b++) acc[b] = 0.f;
    const float* wrow = lin_w + (size_t)o * 8192;
    for (int j = t; j < 8192; j += 256) {
        float w = wrow[j];
#pragma unroll
        for (int b = 0; b < 8; b++) acc[b] = fmaf(w, g_En[b * 8192 + j], acc[b]);
    }
#pragma unroll
    for (int b = 0; b < 8; b++) red[b][t] = acc[b];
    __syncthreads();
    for (int s = 128; s > 0; s >>= 1) {
        if (t < s) {
#pragma unroll
            for (int b = 0; b < 8; b++) red[b][t] += red[b][t + s];
        }
        __syncthreads();
    }
    if (t < 8) {
        float z = red[t][0] + lin_b[o];
        g_ctx[t * 256 + o] = 1.f / (1.f + expf(-z));
    }
}

__global__ void final_kernel(float* __restrict__ out)
{
    __shared__ float tile[32][33];
    int bz = blockIdx.z;
    int d0 = blockIdx.x * 32, n0 = blockIdx.y * 32;
    int tx = threadIdx.x, ty = threadIdx.y;
    const float* h = g_h + (size_t)bz * NQ * 256;
#pragma unroll
    for (int j = 0; j < 32; j += 8)
        tile[ty + j][tx] = h[(size_t)(n0 + ty + j) * 256 + d0 + tx];
    __syncthreads();
    float* ob = out + (size_t)bz * 256 * NQ;
#pragma unroll
    for (int j = 0; j < 32; j += 8)
        ob[(size_t)(d0 + ty + j) * NQ + n0 + tx] = tile[tx][ty + j] * g_ctx[bz * 256 + d0 + ty + j];
}

// ===================== launcher =====================
extern "C" void kernel_launch(void* const* d_in, const int* in_sizes, int n_in,
                              void* d_out, int out_size)
{
    (void)in_sizes; (void)n_in; (void)out_size;
    const float* unknown      = (const float*)d_in[0];
    const float* known        = (const float*)d_in[1];
    const float* unknow_feats = (const float*)d_in[2];
    const float* known_feats  = (const float*)d_in[3];
    const float* conv_w1 = (const float*)d_in[4];
    const float* conv_b1 = (const float*)d_in[5];
    const float* bn_g1 = (const float*)d_in[6];
    const float* bn_b1 = (const float*)d_in[7];
    const float* bn_m1 = (const float*)d_in[8];
    const float* bn_v1 = (const float*)d_in[9];
    const float* conv_w2 = (const float*)d_in[10];
    const float* conv_b2 = (const float*)d_in[11];
    const float* bn_g2 = (const float*)d_in[12];
    const float* bn_b2 = (const float*)d_in[13];
    const float* bn_m2 = (const float*)d_in[14];
    const float* bn_v2 = (const float*)d_in[15];
    const float* enc_cw    = (const float*)d_in[16];
    const float* enc_scale = (const float*)d_in[17];
    const float* lin_w     = (const float*)d_in[18];
    const float* lin_b     = (const float*)d_in[19];
    float* out = (float*)d_out;

    prep_kernel<<<256, 256>>>(conv_b1, bn_g1, bn_b1, bn_m1, bn_v1,
                              conv_b2, bn_g2, bn_b2, bn_m2, bn_v2, enc_cw);
    expand_w_kernel<<<512, 256>>>(conv_w1, conv_w2);
    tr_kf_kernel<<<dim3(64, 8, 8), dim3(32, 8)>>>(known_feats);
    three_nn_kernel<<<dim3(NQ / 64, B_), 256>>>(unknown, known);
    interp_kernel<<<dim3(NQ / 2, B_), 256>>>();
    tr_unk_kernel<<<dim3(NQ / 32, 8, B_), dim3(32, 8)>>>(unknow_feats);
    gemm_mma<1><<<dim3(512, 2), 256>>>();
    gemm_mma<2><<<dim3(512, 2), 256>>>();
    encoding_kernel<<<dim3(NQ / 64, B_), 256>>>(enc_cw, enc_scale);
    enc_fin_kernel<<<B_, 256>>>(enc_cw);
    ctx_gemv_kernel<<<256, 256>>>(lin_w, lin_b);
    final_kernel<<<dim3(8, NQ / 32, B_), dim3(32, 8)>>>(out);
}

// round 7
// speedup vs baseline: 1.2976x; 1.0011x over previous
#include <cuda_runtime.h>
#include <math.h>
#include <stdint.h>

#define B_   8
#define NQ   8192
#define MK   2048
typedef unsigned short ushortT;
typedef unsigned int   uintT;

// ===================== helpers =====================
__device__ __forceinline__ uint32_t smem_to_u32(const void* p) {
    uint32_t a;
    asm("{ .reg .u64 t; cvta.to.shared.u64 t, %1; cvt.u32.u64 %0, t; }" : "=r"(a) : "l"(p));
    return a;
}
#define CP_ASYNC16(s, g) \
    asm volatile("cp.async.cg.shared.global [%0], [%1], 16;" :: "r"(s), "l"(g))
#define CP_COMMIT() asm volatile("cp.async.commit_group;")
#define CP_WAIT2()  asm volatile("cp.async.wait_group 2;")

__device__ __forceinline__ void ldsm4(uint32_t& r0, uint32_t& r1, uint32_t& r2, uint32_t& r3,
                                      uint32_t addr) {
    asm volatile("ldmatrix.sync.aligned.m8n8.x4.shared.b16 {%0,%1,%2,%3}, [%4];"
                 : "=r"(r0), "=r"(r1), "=r"(r2), "=r"(r3) : "r"(addr));
}
__device__ __forceinline__ void ldsm2(uint32_t& r0, uint32_t& r1, uint32_t addr) {
    asm volatile("ldmatrix.sync.aligned.m8n8.x2.shared.b16 {%0,%1}, [%2];"
                 : "=r"(r0), "=r"(r1) : "r"(addr));
}
__device__ __forceinline__ void mma16816(float* d, const uint32_t* a, const uint32_t* b) {
    asm volatile(
        "mma.sync.aligned.m16n8k16.row.col.f32.bf16.bf16.f32 "
        "{%0,%1,%2,%3}, {%4,%5,%6,%7}, {%8,%9}, {%0,%1,%2,%3};"
        : "+f"(d[0]), "+f"(d[1]), "+f"(d[2]), "+f"(d[3])
        : "r"(a[0]), "r"(a[1]), "r"(a[2]), "r"(a[3]), "r"(b[0]), "r"(b[1]));
}

// fp32 -> bf16 hi + bf16 lo (RNE)
__device__ __forceinline__ void split_bf(float v, ushortT& h, ushortT& l) {
    uintT u = __float_as_uint(v);
    uintT hb = (u + 0x7fffu + ((u >> 16) & 1u)) >> 16;
    h = (ushortT)hb;
    float r = v - __uint_as_float(hb << 16);
    uintT u2 = __float_as_uint(r);
    l = (ushortT)((u2 + 0x7fffu + ((u2 >> 16) & 1u)) >> 16);
}

__device__ __forceinline__ void ins3(float& d0, int& i0, float& d1, int& i1,
                                     float& d2, int& i2, float dd, int m) {
    if (dd < d2) {
        if (dd < d1) {
            d2 = d1; i2 = i1;
            if (dd < d0) { d1 = d0; i1 = i0; d0 = dd; i0 = m; }
            else          { d1 = dd; i1 = m; }
        } else { d2 = dd; i2 = m; }
    }
}

// ===================== scratch =====================
__device__ ushortT gA1[(size_t)8 * 8192 * 1024];  // [H(512) | L(512)]
__device__ ushortT gA2[(size_t)8 * 8192 * 512];   // [H(256) | L(256)]
__device__ ushortT gW1[256 * 1536];               // [Wh | Wl | Wh]
__device__ ushortT gW2[256 * 768];
__device__ float g_h  [(size_t)8 * 8192 * 256];
__device__ float g_kfT[(size_t)8 * 2048 * 256];
__device__ int   g_idx[8 * 8192 * 3];
__device__ float g_wgt[8 * 8192 * 3];
__device__ float g_E  [8 * 8192];
__device__ float g_En [8 * 8192];
__device__ float g_sumA[8 * 32];
__device__ float g_ctx[8 * 256];
__device__ float g_al1[256], g_be1[256], g_al2[256], g_be2[256];
__device__ float g_c2[32];

// ===================== prep =====================
__global__ void prep_kernel(const float* __restrict__ cb1, const float* __restrict__ gg1,
                            const float* __restrict__ bb1, const float* __restrict__ mm1,
                            const float* __restrict__ vv1,
                            const float* __restrict__ cb2, const float* __restrict__ gg2,
                            const float* __restrict__ bb2, const float* __restrict__ mm2,
                            const float* __restrict__ vv2,
                            const float* __restrict__ cw)
{
    int i = blockIdx.x * blockDim.x + threadIdx.x;
    if (i < 256) {
        float s1 = gg1[i] * rsqrtf(vv1[i] + 1e-5f);
        g_al1[i] = s1;
        g_be1[i] = s1 * (cb1[i] - mm1[i]) + bb1[i];
        float s2 = gg2[i] * rsqrtf(vv2[i] + 1e-5f);
        g_al2[i] = s2;
        g_be2[i] = s2 * (cb2[i] - mm2[i]) + bb2[i];
    }
    if (i < 32) {
        float s = 0.f;
        const float* c = cw + i * 256;
        for (int d = 0; d < 256; d++) s += c[d] * c[d];
        g_c2[i] = s;
    }
    if (i < 8 * 32) g_sumA[i] = 0.f;
    if (i < 8 * 8192) g_E[i] = 0.f;
}

__global__ void expand_w_kernel(const float* __restrict__ w1, const float* __restrict__ w2)
{
    int i = blockIdx.x * 256 + threadIdx.x;
    if (i < 256 * 512) {
        int n = i >> 9, k = i & 511;
        ushortT h, l; split_bf(w1[i], h, l);
        gW1[n * 1536 + k] = h; gW1[n * 1536 + 512 + k] = l; gW1[n * 1536 + 1024 + k] = h;
    }
    if (i < 256 * 256) {
        int n = i >> 8, k = i & 255;
        ushortT h, l; split_bf(w2[i], h, l);
        gW2[n * 768 + k] = h; gW2[n * 768 + 256 + k] = l; gW2[n * 768 + 512 + k] = h;
    }
}

// ---------------- transpose known_feats (B,256,2048) -> (B,2048,256) ----------------
__global__ void tr_kf_kernel(const float* __restrict__ kf)
{
    __shared__ float tile[32][33];
    int b = blockIdx.z;
    int m0 = blockIdx.x * 32, c0 = blockIdx.y * 32;
    int tx = threadIdx.x, ty = threadIdx.y;
    const float* in = kf + (size_t)b * 256 * MK;
#pragma unroll
    for (int j = 0; j < 32; j += 8)
        tile[ty + j][tx] = in[(size_t)(c0 + ty + j) * MK + m0 + tx];
    __syncthreads();
    float* out = g_kfT + (size_t)b * MK * 256;
#pragma unroll
    for (int j = 0; j < 32; j += 8)
        out[(size_t)(m0 + ty + j) * 256 + c0 + tx] = tile[tx][ty + j];
}

// ---------------- transpose unknow_feats -> gA1 cols [256,512) H, [768,1024) L -------
__global__ void tr_unk_kernel(const float* __restrict__ uf)
{
    __shared__ float tile[32][33];
    int b = blockIdx.z;
    int n0 = blockIdx.x * 32, c0 = blockIdx.y * 32;
    int tx = threadIdx.x, ty = threadIdx.y;
    const float* in = uf + (size_t)b * 256 * NQ;
#pragma unroll
    for (int j = 0; j < 32; j += 8)
        tile[ty + j][tx] = in[(size_t)(c0 + ty + j) * NQ + n0 + tx];
    __syncthreads();
#pragma unroll
    for (int j = 0; j < 32; j += 8) {
        float v = tile[tx][ty + j];
        ushortT h, l; split_bf(v, h, l);
        size_t row = ((size_t)b * NQ + n0 + ty + j) * 1024;
        gA1[row + 256 + c0 + tx] = h;
        gA1[row + 768 + c0 + tx] = l;
    }
}

// ---------------- three_nn: 4 threads/query, padded chunks, 3-FMA inner loop --------
#define CHPAD 513
__global__ __launch_bounds__(256) void three_nn_kernel(const float* __restrict__ unknown,
                                                       const float* __restrict__ known)
{
    __shared__ float4 kp[4 * CHPAD];
    int bz = blockIdx.y;
    int t  = threadIdx.x;
    int q  = blockIdx.x * 64 + (t >> 2);
    int ck = t & 3;

    const float* kb = known + (size_t)bz * MK * 3;
    for (int i = t; i < MK; i += 256) {
        float kx = kb[i * 3 + 0];
        float ky = kb[i * 3 + 1];
        float kz = kb[i * 3 + 2];
        kp[(i >> 9) * CHPAD + (i & 511)] = make_float4(kx, ky, kz, kx * kx + ky * ky + kz * kz);
    }
    __syncthreads();

    const float* u = unknown + ((size_t)bz * NQ + q) * 3;
    float ux = u[0], uy = u[1], uz = u[2];
    float x2 = ux * ux + uy * uy + uz * uz;
    float mux = -2.f * ux, muy = -2.f * uy, muz = -2.f * uz;

    // distance surrogate: dd' = y2 - 2*dot (x2 added back for the winners only)
    float d0 = 1e30f, d1 = 1e30f, d2 = 1e30f;
    int   i0 = 0, i1 = 0, i2 = 0;
    const float4* base = kp + ck * CHPAD;
    int m0 = ck * 512;
#pragma unroll 4
    for (int j = 0; j < 512; j++) {
        float4 p = base[j];
        float dd = fmaf(mux, p.x, p.w);
        dd = fmaf(muy, p.y, dd);
        dd = fmaf(muz, p.z, dd);
        ins3(d0, i0, d1, i1, d2, i2, dd, m0 + j);
    }

#pragma unroll
    for (int off = 1; off <= 2; off <<= 1) {
        float e0 = __shfl_xor_sync(0xffffffffu, d0, off);
        float e1 = __shfl_xor_sync(0xffffffffu, d1, off);
        float e2 = __shfl_xor_sync(0xffffffffu, d2, off);
        int   j0 = __shfl_xor_sync(0xffffffffu, i0, off);
        int   j1 = __shfl_xor_sync(0xffffffffu, i1, off);
        int   j2 = __shfl_xor_sync(0xffffffffu, i2, off);
        ins3(d0, i0, d1, i1, d2, i2, e0, j0);
        ins3(d0, i0, d1, i1, d2, i2, e1, j1);
        ins3(d0, i0, d1, i1, d2, i2, e2, j2);
    }

    if (ck == 0) {
        float r0 = 1.f / (sqrtf(fmaxf(d0 + x2, 1e-12f)) + 1e-8f);
        float r1 = 1.f / (sqrtf(fmaxf(d1 + x2, 1e-12f)) + 1e-8f);
        float r2 = 1.f / (sqrtf(fmaxf(d2 + x2, 1e-12f)) + 1e-8f);
        float rs = 1.f / (r0 + r1 + r2);
        size_t base2 = ((size_t)bz * NQ + q) * 3;
        g_idx[base2 + 0] = i0; g_idx[base2 + 1] = i1; g_idx[base2 + 2] = i2;
        g_wgt[base2 + 0] = r0 * rs; g_wgt[base2 + 1] = r1 * rs; g_wgt[base2 + 2] = r2 * rs;
    }
}

// ---------------- interpolate -> gA1 cols [0,256) H, [512,768) L (4-wide) -----------
__global__ __launch_bounds__(256) void interp_kernel()
{
    int bz = blockIdx.y, t = threadIdx.x;
    int n = blockIdx.x * 4 + (t >> 6);
    int d = (t & 63) * 4;
    size_t base = ((size_t)bz * NQ + n) * 3;
    int i0 = g_idx[base], i1 = g_idx[base + 1], i2 = g_idx[base + 2];
    float w0 = g_wgt[base], w1 = g_wgt[base + 1], w2 = g_wgt[base + 2];
    const float* kf = g_kfT + (size_t)bz * MK * 256;
    float4 a = *(const float4*)&kf[(size_t)i0 * 256 + d];
    float4 b = *(const float4*)&kf[(size_t)i1 * 256 + d];
    float4 c = *(const float4*)&kf[(size_t)i2 * 256 + d];
    float v0 = w0 * a.x + w1 * b.x + w2 * c.x;
    float v1 = w0 * a.y + w1 * b.y + w2 * c.y;
    float v2 = w0 * a.z + w1 * b.z + w2 * c.z;
    float v3 = w0 * a.w + w1 * b.w + w2 * c.w;
    ushortT h0, l0, h1, l1, h2, l2, h3, l3;
    split_bf(v0, h0, l0); split_bf(v1, h1, l1);
    split_bf(v2, h2, l2); split_bf(v3, h3, l3);
    size_t row = ((size_t)bz * NQ + n) * 1024;
    uint2 hp = make_uint2((uintT)h0 | ((uintT)h1 << 16), (uintT)h2 | ((uintT)h3 << 16));
    uint2 lp = make_uint2((uintT)l0 | ((uintT)l1 << 16), (uintT)l2 | ((uintT)l3 << 16));
    *(uint2*)&gA1[row + d]       = hp;
    *(uint2*)&gA1[row + 512 + d] = lp;
}

// ===================== HMMA GEMM (4-stage cp.async pipeline) =====================
template <int L>
__global__ __launch_bounds__(256) void gemm_mma()
{
    constexpr int K   = (L == 1) ? 512 : 256;
    constexpr int CPB = K / 32;
    constexpr int NCH = 3 * CPB;
    constexpr int KA  = 2 * K;
    constexpr int KW  = 3 * K;
    const ushortT* Ag = (L == 1) ? gA1 : gA2;
    const ushortT* Wg = (L == 1) ? gW1 : gW2;
    const float* alpha = (L == 1) ? g_al1 : g_al2;
    const float* beta  = (L == 1) ? g_be1 : g_be2;

    extern __shared__ __align__(16) ushortT dyn[];
    ushortT* sA = dyn;                 // 4 stages x 4096 ushort = 8KB each
    ushortT* sB = dyn + 4 * 4096;
    float* s_al = (float*)(dyn + 8 * 4096);
    float* s_be = s_al + 128;

    int tid = threadIdx.x, wid = tid >> 5, lane = tid & 31;
    int bm = blockIdx.x * 128, bn = blockIdx.y * 128;
    if (tid < 128) { s_al[tid] = alpha[bn + tid]; s_be[tid] = beta[bn + tid]; }

    uint32_t sAb = smem_to_u32(sA);
    uint32_t sBb = smem_to_u32(sB);

    int lr = tid >> 1;
    int ls = (tid & 1) * 2;
    uint32_t off0 = lr * 64 + (((ls)     ^ (lr & 3)) << 4);
    uint32_t off1 = lr * 64 + (((ls + 1) ^ (lr & 3)) << 4);

    const ushortT* Arow = Ag + (size_t)(bm + lr) * KA;
    const ushortT* Wrow = Wg + (size_t)(bn + lr) * KW;

    // prologue: 3 chunks in flight
#pragma unroll
    for (int p = 0; p < 3; p++) {
        int blk = p / CPB;
        int acol = (blk == 2 ? K : 0) + (p % CPB) * 32;
        int wcol = p * 32;
        uint32_t as = sAb + (p & 3) * 8192;
        uint32_t ws = sBb + (p & 3) * 8192;
        CP_ASYNC16(as + off0, Arow + acol + ls * 8);
        CP_ASYNC16(as + off1, Arow + acol + ls * 8 + 8);
        CP_ASYNC16(ws + off0, Wrow + wcol + ls * 8);
        CP_ASYNC16(ws + off1, Wrow + wcol + ls * 8 + 8);
        CP_COMMIT();
    }

    float c[4][4][4];
#pragma unroll
    for (int i = 0; i < 4; i++)
#pragma unroll
        for (int j = 0; j < 4; j++)
#pragma unroll
            for (int q = 0; q < 4; q++) c[i][j][q] = 0.f;

    int wm = wid >> 2, wn = wid & 3;

    for (int kc = 0; kc < NCH; kc++) {
        CP_WAIT2();                 // chunk kc complete (<=2 groups pending)
        __syncthreads();            // ...and visible to all threads; also orders
                                    // last iteration's reads before stage reuse below
        int kn = kc + 3;
        if (kn < NCH) {
            int blk = kn / CPB;
            int acol = (blk == 2 ? K : 0) + (kn % CPB) * 32;
            int wcol = kn * 32;
            uint32_t as = sAb + (kn & 3) * 8192;
            uint32_t ws = sBb + (kn & 3) * 8192;
            CP_ASYNC16(as + off0, Arow + acol + ls * 8);
            CP_ASYNC16(as + off1, Arow + acol + ls * 8 + 8);
            CP_ASYNC16(ws + off0, Wrow + wcol + ls * 8);
            CP_ASYNC16(ws + off1, Wrow + wcol + ls * 8 + 8);
            CP_COMMIT();
        }
        uint32_t aBase = sAb + (kc & 3) * 8192;
        uint32_t bBase = sBb + (kc & 3) * 8192;
#pragma unroll
        for (int kk = 0; kk < 2; kk++) {
            uint32_t afr[4][4], bfr[4][2];
#pragma unroll
            for (int mt = 0; mt < 4; mt++) {
                int r = wm * 64 + mt * 16 + (lane & 15);
                int s = kk * 2 + (lane >> 4);
                ldsm4(afr[mt][0], afr[mt][1], afr[mt][2], afr[mt][3],
                      aBase + r * 64 + ((s ^ (r & 3)) << 4));
            }
#pragma unroll
            for (int nt = 0; nt < 4; nt++) {
                int r = wn * 32 + nt * 8 + (lane & 7);
                int s = kk * 2 + ((lane >> 3) & 1);
                ldsm2(bfr[nt][0], bfr[nt][1],
                      bBase + r * 64 + ((s ^ (r & 3)) << 4));
            }
#pragma unroll
            for (int mt = 0; mt < 4; mt++)
#pragma unroll
                for (int nt = 0; nt < 4; nt++)
                    mma16816(c[mt][nt], afr[mt], bfr[nt]);
        }
    }

#pragma unroll
    for (int mt = 0; mt < 4; mt++) {
#pragma unroll
        for (int nt = 0; nt < 4; nt++) {
            int cl = wn * 32 + nt * 8 + (lane & 3) * 2;
            int gcol = bn + cl;
            int rl = wm * 64 + mt * 16 + (lane >> 2);
#pragma unroll
            for (int hh = 0; hh < 2; hh++) {
                int grow = bm + rl + hh * 8;
                float v0 = fmaxf(fmaf(c[mt][nt][hh * 2 + 0], s_al[cl],     s_be[cl]),     0.f);
                float v1 = fmaxf(fmaf(c[mt][nt][hh * 2 + 1], s_al[cl + 1], s_be[cl + 1]), 0.f);
                if (L == 1) {
                    ushortT h0, l0, h1, l1;
                    split_bf(v0, h0, l0); split_bf(v1, h1, l1);
                    *(uintT*)&gA2[(size_t)grow * 512 + gcol]       = (uintT)h0 | ((uintT)h1 << 16);
                    *(uintT*)&gA2[(size_t)grow * 512 + 256 + gcol] = (uintT)l0 | ((uintT)l1 << 16);
                } else {
                    float2 o = make_float2(v0, v1);
                    *(float2*)&g_h[(size_t)grow * 256 + gcol] = o;
                }
            }
        }
    }
}

// ---------------- encoding ----------------
__global__ __launch_bounds__(256) void encoding_kernel(const float* __restrict__ cw,
                                                       const float* __restrict__ scale)
{
    __shared__ float cwT[256][32];
    __shared__ float Ash[64][32];
    __shared__ float c2s[32], scs[32];
    int bz = blockIdx.y;
    int n0 = blockIdx.x * 64;
    int t = threadIdx.x, warp = t >> 5, lane = t & 31;
    for (int i = t; i < 32 * 256; i += 256) cwT[i & 255][i >> 8] = cw[i];
    if (t < 32) { c2s[t] = g_c2[t]; scs[t] = scale[t]; }
    __syncthreads();
    const float* Xb = g_h + ((size_t)bz * NQ + n0) * 256;
    for (int pi = 0; pi < 8; pi++) {
        int p = warp * 8 + pi;
        const float* xp = Xb + (size_t)p * 256;
        float xr[8];
#pragma unroll
        for (int j = 0; j < 8; j++) xr[j] = xp[j * 32 + lane];
        float xn2 = 0.f;
#pragma unroll
        for (int j = 0; j < 8; j++) xn2 = fmaf(xr[j], xr[j], xn2);
#pragma unroll
        for (int o = 16; o > 0; o >>= 1) xn2 += __shfl_xor_sync(0xffffffffu, xn2, o);
        float dotv = 0.f;
#pragma unroll
        for (int j = 0; j < 8; j++) {
            float xj = xr[j];
#pragma unroll
            for (int l2 = 0; l2 < 32; l2++) {
                float x = __shfl_sync(0xffffffffu, xj, l2);
                dotv = fmaf(x, cwT[j * 32 + l2][lane], dotv);
            }
        }
        float sl = scs[lane] * (xn2 - 2.f * dotv + c2s[lane]);
        float mx = sl;
#pragma unroll
        for (int o = 16; o > 0; o >>= 1) mx = fmaxf(mx, __shfl_xor_sync(0xffffffffu, mx, o));
        float e = __expf(sl - mx);
        float se = e;
#pragma unroll
        for (int o = 16; o > 0; o >>= 1) se += __shfl_xor_sync(0xffffffffu, se, o);
        Ash[p][lane] = e / se;
    }
    __syncthreads();
    if (t < 32) {
        float s = 0.f;
        for (int p = 0; p < 64; p++) s += Ash[p][t];
        atomicAdd(&g_sumA[bz * 32 + t], s);
    }
    float acc[32];
#pragma unroll
    for (int k = 0; k < 32; k++) acc[k] = 0.f;
    for (int p = 0; p < 64; p++) {
        float x = Xb[(size_t)p * 256 + t];
#pragma unroll
        for (int k = 0; k < 32; k++) acc[k] = fmaf(Ash[p][k], x, acc[k]);
    }
    float* Eb = g_E + (size_t)bz * 8192;
#pragma unroll
    for (int k = 0; k < 32; k++) atomicAdd(&Eb[k * 256 + t], acc[k]);
}

__global__ __launch_bounds__(256) void enc_fin_kernel(const float* __restrict__ cw)
{
    __shared__ float red[256];
    int bz = blockIdx.x, t = threadIdx.x;
    float ss = 0.f;
    for (int j = t; j < 8192; j += 256) {
        float v = g_E[bz * 8192 + j] - g_sumA[bz * 32 + (j >> 8)] * cw[j];
        v = fmaxf(v, 0.f);
        g_En[bz * 8192 + j] = v;
        ss += v * v;
    }
    red[t] = ss;
    __syncthreads();
    for (int s = 128; s > 0; s >>= 1) {
        if (t < s) red[t] += red[t + s];
        __syncthreads();
    }
    float rinv = 1.f / fmaxf(sqrtf(red[0]), 1e-12f);
    for (int j = t; j < 8192; j += 256) g_En[bz * 8192 + j] *= rinv;
}

__global__ __launch_bounds__(256) void ctx_gemv_kernel(const float* __restrict__ lin_w,
                                                       const float* __restrict__ lin_b)
{
    __shared__ float red[8][256];
    int o = blockIdx.x, t = threadIdx.x;
    float acc[8];
#pragma unroll
    for (int b = 0; b < 8; b++) acc[b] = 0.f;
    const float* wrow = lin_w + (size_t)o * 8192;
    for (int j = t; j < 8192; j += 256) {
        float w = wrow[j];
#pragma unroll
        for (int b = 0; b < 8; b++) acc[b] = fmaf(w, g_En[b * 8192 + j], acc[b]);
    }
#pragma unroll
    for (int b = 0; b < 8; b++) red[b][t] = acc[b];
    __syncthreads();
    for (int s = 128; s > 0; s >>= 1) {
        if (t < s) {
#pragma unroll
            for (int b = 0; b < 8; b++) red[b][t] += red[b][t + s];
        }
        __syncthreads();
    }
    if (t < 8) {
        float z = red[t][0] + lin_b[o];
        g_ctx[t * 256 + o] = 1.f / (1.f + expf(-z));
    }
}

__global__ void final_kernel(float* __restrict__ out)
{
    __shared__ float tile[32][33];
    int bz = blockIdx.z;
    int d0 = blockIdx.x * 32, n0 = blockIdx.y * 32;
    int tx = threadIdx.x, ty = threadIdx.y;
    const float* h = g_h + (size_t)bz * NQ * 256;
#pragma unroll
    for (int j = 0; j < 32; j += 8)
        tile[ty + j][tx] = h[(size_t)(n0 + ty + j) * 256 + d0 + tx];
    __syncthreads();
    float* ob = out + (size_t)bz * 256 * NQ;
#pragma unroll
    for (int j = 0; j < 32; j += 8)
        ob[(size_t)(d0 + ty + j) * NQ + n0 + tx] = tile[tx][ty + j] * g_ctx[bz * 256 + d0 + ty + j];
}

// ===================== launcher =====================
extern "C" void kernel_launch(void* const* d_in, const int* in_sizes, int n_in,
                              void* d_out, int out_size)
{
    (void)in_sizes; (void)n_in; (void)out_size;
    const float* unknown      = (const float*)d_in[0];
    const float* known        = (const float*)d_in[1];
    const float* unknow_feats = (const float*)d_in[2];
    const float* known_feats  = (const float*)d_in[3];
    const float* conv_w1 = (const float*)d_in[4];
    const float* conv_b1 = (const float*)d_in[5];
    const float* bn_g1 = (const float*)d_in[6];
    const float* bn_b1 = (const float*)d_in[7];
    const float* bn_m1 = (const float*)d_in[8];
    const float* bn_v1 = (const float*)d_in[9];
    const float* conv_w2 = (const float*)d_in[10];
    const float* conv_b2 = (const float*)d_in[11];
    const float* bn_g2 = (const float*)d_in[12];
    const float* bn_b2 = (const float*)d_in[13];
    const float* bn_m2 = (const float*)d_in[14];
    const float* bn_v2 = (const float*)d_in[15];
    const float* enc_cw    = (const float*)d_in[16];
    const float* enc_scale = (const float*)d_in[17];
    const float* lin_w     = (const float*)d_in[18];
    const float* lin_b     = (const float*)d_in[19];
    float* out = (float*)d_out;

    const int SMEMSZ = 4 * 16384 + 1024;   // 4 stages (A+B) + alpha/beta
    static int attr_done = 0;
    if (!attr_done) {
        cudaFuncSetAttribute(gemm_mma<1>, cudaFuncAttributeMaxDynamicSharedMemorySize, SMEMSZ);
        cudaFuncSetAttribute(gemm_mma<2>, cudaFuncAttributeMaxDynamicSharedMemorySize, SMEMSZ);
        attr_done = 1;
    }

    prep_kernel<<<256, 256>>>(conv_b1, bn_g1, bn_b1, bn_m1, bn_v1,
                              conv_b2, bn_g2, bn_b2, bn_m2, bn_v2, enc_cw);
    expand_w_kernel<<<512, 256>>>(conv_w1, conv_w2);
    tr_kf_kernel<<<dim3(64, 8, 8), dim3(32, 8)>>>(known_feats);
    three_nn_kernel<<<dim3(NQ / 64, B_), 256>>>(unknown, known);
    interp_kernel<<<dim3(NQ / 4, B_), 256>>>();
    tr_unk_kernel<<<dim3(NQ / 32, 8, B_), dim3(32, 8)>>>(unknow_feats);
    gemm_mma<1><<<dim3(512, 2), 256, SMEMSZ>>>();
    gemm_mma<2><<<dim3(512, 2), 256, SMEMSZ>>>();
    encoding_kernel<<<dim3(NQ / 64, B_), 256>>>(enc_cw, enc_scale);
    enc_fin_kernel<<<B_, 256>>>(enc_cw);
    ctx_gemv_kernel<<<256, 256>>>(lin_w, lin_b);
    final_kernel<<<dim3(8, NQ / 32, B_), dim3(32, 8)>>>(out);
}